// round 1
// baseline (speedup 1.0000x reference)
#include <cuda_runtime.h>
#include <cuda_bf16.h>
#include <cstddef>

// Problem constants
constexpr int N_BATCH = 256;
constexpr int C = 128;          // in = out channels for all layers
constexpr int L0 = 1024;
constexpr int L1 = 505;         // (1024-15)/2+1
constexpr int L2 = 247;         // (505-12)/2+1
constexpr int L3 = 121;         // (247-7)/2+1
constexpr int L4 = 59;          // (121-4)/2+1
constexpr int D = C * L4;       // 7552
constexpr int KC = 64;          // number of centers

// Intermediate activation buffers (device globals -- no allocation allowed)
__device__ float g_h1[(size_t)N_BATCH * C * L1];
__device__ float g_h2[(size_t)N_BATCH * C * L2];
__device__ float g_h3[(size_t)N_BATCH * C * L3];
__device__ float g_h4[(size_t)N_BATCH * C * L4];

// ---------------------------------------------------------------------------
// Conv1d (stride 2, VALID) as implicit GEMM.
// Block tile: all 128 output channels x TL=64 output positions, one batch n.
// Thread tile: 8 channels x 4 positions (256 threads).
// Input tile (128 x (2*TL+K-2)) staged in SMEM once per block; weights staged
// per input-channel chunk (K x 128, [k][o] layout) through SMEM.
// ---------------------------------------------------------------------------
template<int K, int L_IN, int L_OUT, bool RELU>
__global__ void __launch_bounds__(256, 2)
conv_kernel(const float* __restrict__ x, const float* __restrict__ w,
            const float* __restrict__ b, float* __restrict__ out)
{
    constexpr int TL  = 64;
    constexpr int WX  = 2 * TL + K - 2;          // input span covered by tile
    constexpr int WXP = (WX + 3) & ~3;           // padded row stride (floats)
    constexpr int M   = C * K;                   // GEMM K-dim (per out elem)
    constexpr int WSP = 132;                     // ws row stride (mult of 4)

    extern __shared__ float sm[];
    float* xs = sm;                 // [C][WXP]
    float* ws = sm + C * WXP;       // [K][WSP] : ws[k*WSP + o]

    const int n   = blockIdx.y;
    const int l0  = blockIdx.x * TL;
    const int tid = threadIdx.x;

    // ---- load input tile ----
    const float* xn = x + (size_t)n * C * L_IN;
    for (int idx = tid; idx < C * WX; idx += 256) {
        int i = idx / WX;
        int t = idx - i * WX;
        int pos = 2 * l0 + t;
        xs[i * WXP + t] = (pos < L_IN) ? xn[i * L_IN + pos] : 0.0f;
    }

    // thread tile coordinates
    const int to = (tid & 15) * 8;   // output-channel base (0..120)
    const int tl = (tid >> 4) * 4;   // local position base (0..60)

    float acc[8][4];
    #pragma unroll
    for (int a = 0; a < 8; a++)
        #pragma unroll
        for (int j = 0; j < 4; j++) acc[a][j] = 0.0f;

    // ---- main loop over input channels ----
    for (int i = 0; i < C; i++) {
        __syncthreads();   // protect ws (prev iter) and (first iter) xs stores
        // stage W[:, i, :] as ws[k][o]
        for (int idx = tid; idx < K * C; idx += 256) {
            int o = idx / K;
            int k = idx - o * K;
            ws[k * WSP + o] = w[(size_t)o * M + i * K + k];
        }
        __syncthreads();

        const float* xrow = xs + i * WXP + 2 * tl;
        #pragma unroll
        for (int k = 0; k < K; k++) {
            const float4 wa = *reinterpret_cast<const float4*>(&ws[k * WSP + to]);
            const float4 wb = *reinterpret_cast<const float4*>(&ws[k * WSP + to + 4]);
            float xv[4];
            #pragma unroll
            for (int j = 0; j < 4; j++) xv[j] = xrow[2 * j + k];
            #pragma unroll
            for (int j = 0; j < 4; j++) {
                acc[0][j] = fmaf(wa.x, xv[j], acc[0][j]);
                acc[1][j] = fmaf(wa.y, xv[j], acc[1][j]);
                acc[2][j] = fmaf(wa.z, xv[j], acc[2][j]);
                acc[3][j] = fmaf(wa.w, xv[j], acc[3][j]);
                acc[4][j] = fmaf(wb.x, xv[j], acc[4][j]);
                acc[5][j] = fmaf(wb.y, xv[j], acc[5][j]);
                acc[6][j] = fmaf(wb.z, xv[j], acc[6][j]);
                acc[7][j] = fmaf(wb.w, xv[j], acc[7][j]);
            }
        }
    }

    // ---- epilogue: bias + LeakyReLU + store ----
    float* on = out + (size_t)n * C * L_OUT;
    #pragma unroll
    for (int a = 0; a < 8; a++) {
        const float bv = b[to + a];
        #pragma unroll
        for (int j = 0; j < 4; j++) {
            int l = l0 + tl + j;
            if (l < L_OUT) {
                float v = acc[a][j] + bv;
                if (RELU) v = (v > 0.0f) ? v : 0.1f * v;
                on[(to + a) * L_OUT + l] = v;
            }
        }
    }
}

// ---------------------------------------------------------------------------
// Distance + Student-t soft assignment.
// One block per sample n. z row (7552 floats) cached in SMEM; each warp owns
// 8 centers, lanes stride over D, warp shuffle reduce.
// alpha = 1 -> q_k = (1 + d2_k)^-1, normalized over k.
// ---------------------------------------------------------------------------
__global__ void __launch_bounds__(256)
dist_kernel(const float* __restrict__ z, const float* __restrict__ cen,
            float* __restrict__ q)
{
    __shared__ float zs[D];
    __shared__ float d2s[KC];
    __shared__ float qv[KC];
    __shared__ float ssum;

    const int tid = threadIdx.x;
    const int n   = blockIdx.x;

    const float* zr = z + (size_t)n * D;
    for (int idx = tid; idx < D; idx += 256) zs[idx] = zr[idx];
    __syncthreads();

    const int warp = tid >> 5;
    const int lane = tid & 31;

    #pragma unroll
    for (int cc = 0; cc < 8; cc++) {
        const int c = warp * 8 + cc;
        const float* cr = cen + (size_t)c * D;
        float s = 0.0f;
        #pragma unroll 4
        for (int idx = lane; idx < D; idx += 32) {
            float df = zs[idx] - cr[idx];
            s = fmaf(df, df, s);
        }
        #pragma unroll
        for (int off = 16; off; off >>= 1)
            s += __shfl_xor_sync(0xffffffffu, s, off);
        if (lane == 0) d2s[c] = s;
    }
    __syncthreads();

    if (tid < KC) qv[tid] = 1.0f / (1.0f + d2s[tid]);
    __syncthreads();

    if (tid < 32) {
        float s = qv[tid] + qv[tid + 32];
        #pragma unroll
        for (int off = 16; off; off >>= 1)
            s += __shfl_xor_sync(0xffffffffu, s, off);
        if (tid == 0) ssum = s;
    }
    __syncthreads();

    if (tid < KC) q[(size_t)n * KC + tid] = qv[tid] / ssum;
}

// ---------------------------------------------------------------------------
// Launch
// ---------------------------------------------------------------------------
template<int K>
static constexpr int conv_smem_bytes() {
    constexpr int TL  = 64;
    constexpr int WX  = 2 * TL + K - 2;
    constexpr int WXP = (WX + 3) & ~3;
    return (C * WXP + K * 132) * (int)sizeof(float);
}

extern "C" void kernel_launch(void* const* d_in, const int* in_sizes, int n_in,
                              void* d_out, int out_size)
{
    const float* x   = (const float*)d_in[0];
    const float* w1  = (const float*)d_in[1];
    const float* b1  = (const float*)d_in[2];
    const float* w2  = (const float*)d_in[3];
    const float* b2  = (const float*)d_in[4];
    const float* w3  = (const float*)d_in[5];
    const float* b3  = (const float*)d_in[6];
    const float* w4  = (const float*)d_in[7];
    const float* b4  = (const float*)d_in[8];
    const float* cen = (const float*)d_in[9];
    float* q = (float*)d_out;

    float* h1; cudaGetSymbolAddress((void**)&h1, g_h1);
    float* h2; cudaGetSymbolAddress((void**)&h2, g_h2);
    float* h3; cudaGetSymbolAddress((void**)&h3, g_h3);
    float* h4; cudaGetSymbolAddress((void**)&h4, g_h4);

    // Opt into >48KB dynamic SMEM (host-side attribute set, not captured)
    cudaFuncSetAttribute(conv_kernel<15, L0, L1, true>,
        cudaFuncAttributeMaxDynamicSharedMemorySize, conv_smem_bytes<15>());
    cudaFuncSetAttribute(conv_kernel<12, L1, L2, true>,
        cudaFuncAttributeMaxDynamicSharedMemorySize, conv_smem_bytes<12>());
    cudaFuncSetAttribute(conv_kernel<7,  L2, L3, true>,
        cudaFuncAttributeMaxDynamicSharedMemorySize, conv_smem_bytes<7>());
    cudaFuncSetAttribute(conv_kernel<4,  L3, L4, false>,
        cudaFuncAttributeMaxDynamicSharedMemorySize, conv_smem_bytes<4>());

    conv_kernel<15, L0, L1, true ><<<dim3((L1 + 63) / 64, N_BATCH), 256,
        conv_smem_bytes<15>()>>>(x,  w1, b1, h1);
    conv_kernel<12, L1, L2, true ><<<dim3((L2 + 63) / 64, N_BATCH), 256,
        conv_smem_bytes<12>()>>>(h1, w2, b2, h2);
    conv_kernel<7,  L2, L3, true ><<<dim3((L3 + 63) / 64, N_BATCH), 256,
        conv_smem_bytes<7>()>>>(h2, w3, b3, h3);
    conv_kernel<4,  L3, L4, false><<<dim3((L4 + 63) / 64, N_BATCH), 256,
        conv_smem_bytes<4>()>>>(h3, w4, b4, h4);

    dist_kernel<<<N_BATCH, 256>>>(h4, cen, q);
}

// round 2
// speedup vs baseline: 1.0747x; 1.0747x over previous
#include <cuda_runtime.h>
#include <cuda_bf16.h>
#include <cstddef>

// Problem constants
constexpr int N_BATCH = 256;
constexpr int C = 128;          // in = out channels for all layers
constexpr int L0 = 1024;
constexpr int L1 = 505;         // (1024-15)/2+1
constexpr int L2 = 247;         // (505-12)/2+1
constexpr int L3 = 121;         // (247-7)/2+1
constexpr int L4 = 59;          // (121-4)/2+1
constexpr int D = C * L4;       // 7552
constexpr int KC = 64;          // number of centers

// Intermediate activation buffers (device globals -- no allocation allowed)
__device__ float g_h1[(size_t)N_BATCH * C * L1];
__device__ float g_h2[(size_t)N_BATCH * C * L2];
__device__ float g_h3[(size_t)N_BATCH * C * L3];
__device__ float g_h4[(size_t)N_BATCH * C * L4];

// ---- packed fp32x2 helpers (FFMA2: only reachable via PTX fma.rn.f32x2) ----
__device__ __forceinline__ unsigned long long dup2(float v) {
    unsigned long long r;
    asm("mov.b64 %0, {%1, %1};" : "=l"(r) : "f"(v));
    return r;
}
__device__ __forceinline__ void fma2(unsigned long long& d,
                                     unsigned long long a,
                                     unsigned long long b) {
    asm("fma.rn.f32x2 %0, %1, %2, %0;" : "+l"(d) : "l"(a), "l"(b));
}
__device__ __forceinline__ void unpack2(unsigned long long v, float& lo, float& hi) {
    asm("mov.b64 {%0, %1}, %2;" : "=f"(lo), "=f"(hi) : "l"(v));
}

// ---------------------------------------------------------------------------
// Conv1d (stride 2, VALID) as implicit GEMM with packed f32x2 math.
// Block tile: OCB output channels x TL=64 positions, one batch sample.
// Thread tile: CPT=OCB/16 channels x 4 positions (256 threads), accumulators
// packed over channel pairs (weight pairs come free from float4 SMEM loads;
// x values duplicated once per input channel into a packed register cache).
// Weights double-buffered in SMEM -> one __syncthreads per input channel.
// ---------------------------------------------------------------------------
template<int K, int L_IN, int L_OUT, bool RELU, int OCB>
__global__ void __launch_bounds__(256, 2)
conv_kernel(const float* __restrict__ x, const float* __restrict__ w,
            const float* __restrict__ b, float* __restrict__ out)
{
    constexpr int TL    = 64;
    constexpr int WX    = 2 * TL + K - 2;        // input span of the tile
    constexpr int WXP   = (WX + 3) & ~3;         // padded row stride
    constexpr int WSP   = OCB + 4;               // ws row stride
    constexpr int CPT   = OCB / 16;              // channels per thread (8 or 4)
    constexpr int PAIRS = CPT / 2;
    constexpr int NV    = K + 6;                 // packed x values per channel
    constexpr int NLD   = (NV + 3) / 4;          // float4 loads for them

    extern __shared__ float sm[];
    float* xs = sm;                    // [C][WXP]
    float* ws = sm + C * WXP;          // [2][K][WSP]

    const int n   = blockIdx.y;
    const int l0  = blockIdx.x * TL;
    const int oc0 = blockIdx.z * OCB;
    const int tid = threadIdx.x;

    // ---- load input tile ----
    const float* xn = x + (size_t)n * C * L_IN;
    for (int idx = tid; idx < C * WX; idx += 256) {
        int i = idx / WX;
        int t = idx - i * WX;
        int pos = 2 * l0 + t;
        xs[i * WXP + t] = (pos < L_IN) ? xn[i * L_IN + pos] : 0.0f;
    }

    // thread tile coordinates
    const int to = (tid & 15) * CPT;   // local output-channel base
    const int tl = (tid >> 4) * 4;     // local position base (0..60)

    unsigned long long acc[PAIRS][4];
    #pragma unroll
    for (int p = 0; p < PAIRS; p++)
        #pragma unroll
        for (int j = 0; j < 4; j++) acc[p][j] = 0ull;

    // weight staging helper: W[oc0+o][i][k] -> wbuf[k*WSP + o]
    auto stage = [&](int i, float* wbuf) {
        for (int idx = tid; idx < K * OCB; idx += 256) {
            int o = idx / K;
            int k = idx - o * K;
            wbuf[k * WSP + o] = w[(size_t)(oc0 + o) * (C * K) + i * K + k];
        }
    };

    stage(0, ws);
    __syncthreads();   // also covers xs tile stores

    for (int i = 0; i < C; i++) {
        float* cur = ws + (i & 1) * (K * WSP);
        float* nxt = ws + ((i + 1) & 1) * (K * WSP);
        if (i + 1 < C) stage(i + 1, nxt);   // safe: readers of nxt synced last iter

        // per-channel x cache, duplicated into packed pairs
        const float* xrow = xs + i * WXP + 2 * tl;
        float xv[NLD * 4];
        #pragma unroll
        for (int t = 0; t < NLD; t++)
            *reinterpret_cast<float4*>(&xv[4 * t]) =
                *reinterpret_cast<const float4*>(xrow + 4 * t);
        unsigned long long xd[NV];
        #pragma unroll
        for (int t = 0; t < NV; t++) xd[t] = dup2(xv[t]);

        #pragma unroll
        for (int k = 0; k < K; k++) {
            const float* wr = cur + k * WSP + to;
            union { float4 f4[CPT / 4]; unsigned long long u[PAIRS]; } wu;
            #pragma unroll
            for (int t = 0; t < CPT / 4; t++)
                wu.f4[t] = *reinterpret_cast<const float4*>(wr + 4 * t);
            #pragma unroll
            for (int p = 0; p < PAIRS; p++) {
                #pragma unroll
                for (int j = 0; j < 4; j++)
                    fma2(acc[p][j], wu.u[p], xd[2 * j + k]);
            }
        }
        __syncthreads();
    }

    // ---- epilogue: bias + LeakyReLU + store ----
    float* on = out + (size_t)n * C * L_OUT + (size_t)(oc0 + to) * L_OUT;
    #pragma unroll
    for (int p = 0; p < PAIRS; p++) {
        const float b0 = b[oc0 + to + 2 * p];
        const float b1 = b[oc0 + to + 2 * p + 1];
        #pragma unroll
        for (int j = 0; j < 4; j++) {
            int l = l0 + tl + j;
            if (l < L_OUT) {
                float lo, hi;
                unpack2(acc[p][j], lo, hi);
                float v0 = lo + b0;
                float v1 = hi + b1;
                if (RELU) {
                    v0 = (v0 > 0.0f) ? v0 : 0.1f * v0;
                    v1 = (v1 > 0.0f) ? v1 : 0.1f * v1;
                }
                on[(2 * p) * L_OUT + l]     = v0;
                on[(2 * p + 1) * L_OUT + l] = v1;
            }
        }
    }
}

// ---------------------------------------------------------------------------
// Distance + Student-t soft assignment (alpha=1).
// ---------------------------------------------------------------------------
__global__ void __launch_bounds__(256)
dist_kernel(const float* __restrict__ z, const float* __restrict__ cen,
            float* __restrict__ q)
{
    __shared__ float zs[D];
    __shared__ float d2s[KC];
    __shared__ float qv[KC];
    __shared__ float ssum;

    const int tid = threadIdx.x;
    const int n   = blockIdx.x;

    const float* zr = z + (size_t)n * D;
    for (int idx = tid; idx < D; idx += 256) zs[idx] = zr[idx];
    __syncthreads();

    const int warp = tid >> 5;
    const int lane = tid & 31;

    #pragma unroll
    for (int cc = 0; cc < 8; cc++) {
        const int c = warp * 8 + cc;
        const float* cr = cen + (size_t)c * D;
        float s = 0.0f;
        #pragma unroll 4
        for (int idx = lane; idx < D; idx += 32) {
            float df = zs[idx] - cr[idx];
            s = fmaf(df, df, s);
        }
        #pragma unroll
        for (int off = 16; off; off >>= 1)
            s += __shfl_xor_sync(0xffffffffu, s, off);
        if (lane == 0) d2s[c] = s;
    }
    __syncthreads();

    if (tid < KC) qv[tid] = 1.0f / (1.0f + d2s[tid]);
    __syncthreads();

    if (tid < 32) {
        float s = qv[tid] + qv[tid + 32];
        #pragma unroll
        for (int off = 16; off; off >>= 1)
            s += __shfl_xor_sync(0xffffffffu, s, off);
        if (tid == 0) ssum = s;
    }
    __syncthreads();

    if (tid < KC) q[(size_t)n * KC + tid] = qv[tid] / ssum;
}

// ---------------------------------------------------------------------------
// Launch
// ---------------------------------------------------------------------------
template<int K, int OCB>
static constexpr int conv_smem_bytes() {
    constexpr int TL  = 64;
    constexpr int WX  = 2 * TL + K - 2;
    constexpr int WXP = (WX + 3) & ~3;
    constexpr int WSP = OCB + 4;
    return (C * WXP + 2 * K * WSP) * (int)sizeof(float);
}

extern "C" void kernel_launch(void* const* d_in, const int* in_sizes, int n_in,
                              void* d_out, int out_size)
{
    const float* x   = (const float*)d_in[0];
    const float* w1  = (const float*)d_in[1];
    const float* b1  = (const float*)d_in[2];
    const float* w2  = (const float*)d_in[3];
    const float* b2  = (const float*)d_in[4];
    const float* w3  = (const float*)d_in[5];
    const float* b3  = (const float*)d_in[6];
    const float* w4  = (const float*)d_in[7];
    const float* b4  = (const float*)d_in[8];
    const float* cen = (const float*)d_in[9];
    float* q = (float*)d_out;

    float* h1; cudaGetSymbolAddress((void**)&h1, g_h1);
    float* h2; cudaGetSymbolAddress((void**)&h2, g_h2);
    float* h3; cudaGetSymbolAddress((void**)&h3, g_h3);
    float* h4; cudaGetSymbolAddress((void**)&h4, g_h4);

    cudaFuncSetAttribute(conv_kernel<15, L0, L1, true, 128>,
        cudaFuncAttributeMaxDynamicSharedMemorySize, conv_smem_bytes<15, 128>());
    cudaFuncSetAttribute(conv_kernel<12, L1, L2, true, 128>,
        cudaFuncAttributeMaxDynamicSharedMemorySize, conv_smem_bytes<12, 128>());
    cudaFuncSetAttribute(conv_kernel<7,  L2, L3, true, 128>,
        cudaFuncAttributeMaxDynamicSharedMemorySize, conv_smem_bytes<7, 128>());
    cudaFuncSetAttribute(conv_kernel<4,  L3, L4, false, 64>,
        cudaFuncAttributeMaxDynamicSharedMemorySize, conv_smem_bytes<4, 64>());

    conv_kernel<15, L0, L1, true, 128><<<dim3((L1 + 63) / 64, N_BATCH, 1), 256,
        conv_smem_bytes<15, 128>()>>>(x,  w1, b1, h1);
    conv_kernel<12, L1, L2, true, 128><<<dim3((L2 + 63) / 64, N_BATCH, 1), 256,
        conv_smem_bytes<12, 128>()>>>(h1, w2, b2, h2);
    conv_kernel<7,  L2, L3, true, 128><<<dim3((L3 + 63) / 64, N_BATCH, 1), 256,
        conv_smem_bytes<7, 128>()>>>(h2, w3, b3, h3);
    conv_kernel<4,  L3, L4, false, 64><<<dim3(1, N_BATCH, 2), 256,
        conv_smem_bytes<4, 64>()>>>(h3, w4, b4, h4);

    dist_kernel<<<N_BATCH, 256>>>(h4, cen, q);
}

// round 3
// speedup vs baseline: 1.6860x; 1.5688x over previous
#include <cuda_runtime.h>
#include <cuda_bf16.h>
#include <cstddef>

// Problem constants
constexpr int N_BATCH = 256;
constexpr int C = 128;
constexpr int L0 = 1024;
constexpr int L1 = 505;
constexpr int L2 = 247;
constexpr int L3 = 121;
constexpr int L4 = 59;
constexpr int D = C * L4;       // 7552
constexpr int KC = 64;

__device__ float g_h1[(size_t)N_BATCH * C * L1];
__device__ float g_h2[(size_t)N_BATCH * C * L2];
__device__ float g_h3[(size_t)N_BATCH * C * L3];
__device__ float g_h4[(size_t)N_BATCH * C * L4];

// ---- packed fp32x2 helpers ----
__device__ __forceinline__ unsigned long long dup2(float v) {
    unsigned long long r;
    asm("mov.b64 %0, {%1, %1};" : "=l"(r) : "f"(v));
    return r;
}
__device__ __forceinline__ void fma2(unsigned long long& d,
                                     unsigned long long a,
                                     unsigned long long b) {
    asm("fma.rn.f32x2 %0, %1, %2, %0;" : "+l"(d) : "l"(a), "l"(b));
}
__device__ __forceinline__ void unpack2(unsigned long long v, float& lo, float& hi) {
    asm("mov.b64 {%0, %1}, %2;" : "=f"(lo), "=f"(hi) : "l"(v));
}

// ---- cp.async helpers ----
__device__ __forceinline__ void cp4(float* dst, const float* src) {
    unsigned saddr = (unsigned)__cvta_generic_to_shared(dst);
    asm volatile("cp.async.ca.shared.global [%0], [%1], 4;"
                 :: "r"(saddr), "l"(src) : "memory");
}
__device__ __forceinline__ void cp_commit() {
    asm volatile("cp.async.commit_group;" ::: "memory");
}
__device__ __forceinline__ void cp_wait2() {
    asm volatile("cp.async.wait_group 2;" ::: "memory");
}

// ---------------------------------------------------------------------------
// Conv1d (stride 2, VALID) as implicit GEMM, packed f32x2 math.
// Block: OCB output channels x TL=64 positions, one sample. 128 threads.
// Thread tile: CPT channels x 8 positions. Weights staged per input channel
// via cp.async into a 4-slot SMEM ring (prefetch distance 2) -> the L2 fetch
// latency never sits on the critical path; ONE __syncthreads per channel.
// ---------------------------------------------------------------------------
template<int K, int L_IN, int L_OUT, bool RELU, int OCB>
__global__ void __launch_bounds__(128, 2)
conv_kernel(const float* __restrict__ x, const float* __restrict__ w,
            const float* __restrict__ b, float* __restrict__ out)
{
    constexpr int TL    = 64;
    constexpr int WX    = 2 * TL + K - 2;
    constexpr int WXP   = (WX + 3) & ~3;
    constexpr int WSP   = OCB + 4;
    constexpr int CPT   = OCB / 16;      // 8 or 4
    constexpr int PAIRS = CPT / 2;       // 4 or 2
    constexpr int NV    = K + 14;        // packed x values per channel
    constexpr int NLD   = (NV + 3) / 4;
    constexpr int KW    = K * WSP;       // one ring slot, floats

    extern __shared__ float sm[];
    float* xs = sm;                 // [C][WXP]
    float* ws = sm + C * WXP;       // [4][K][WSP]

    const int n   = blockIdx.y;
    const int l0  = blockIdx.x * TL;
    const int oc0 = blockIdx.z * OCB;
    const int tid = threadIdx.x;

    // ---- input tile -> SMEM ----
    const float* xn = x + (size_t)n * C * L_IN;
    for (int idx = tid; idx < C * WX; idx += 128) {
        int i = idx / WX;
        int t = idx - i * WX;
        int pos = 2 * l0 + t;
        xs[i * WXP + t] = (pos < L_IN) ? xn[i * L_IN + pos] : 0.0f;
    }

    const int to = (tid & 15) * CPT;   // local oc base
    const int tl = (tid >> 4) * 8;     // local position base (0..56)

    unsigned long long acc[PAIRS][8];
    #pragma unroll
    for (int p = 0; p < PAIRS; p++)
        #pragma unroll
        for (int j = 0; j < 8; j++) acc[p][j] = 0ull;

    // async weight staging: W[oc0+o][i][k] -> buf[k*WSP + o]
    auto stage = [&](int i, float* buf) {
        const float* wsrc = w + (size_t)oc0 * (C * K) + i * K;
        #pragma unroll 4
        for (int idx = tid; idx < K * OCB; idx += 128) {
            int o = idx / K;
            int k = idx - o * K;
            cp4(&buf[k * WSP + o], wsrc + (size_t)o * (C * K) + k);
        }
    };

    stage(0, ws);            cp_commit();
    stage(1, ws + KW);       cp_commit();

    for (int i = 0; i < C; i++) {
        if (i + 2 < C) stage(i + 2, ws + ((i + 2) & 3) * KW);
        cp_commit();
        cp_wait2();          // group i landed (this thread)
        __syncthreads();     // all threads' group i visible; xs ready (i==0)

        const float* cur = ws + (i & 3) * KW;

        // per-channel packed x cache
        const float* xrow = xs + i * WXP + 2 * tl;
        float xv[NLD * 4];
        #pragma unroll
        for (int t = 0; t < NLD; t++)
            *reinterpret_cast<float4*>(&xv[4 * t]) =
                *reinterpret_cast<const float4*>(xrow + 4 * t);
        unsigned long long xd[NV];
        #pragma unroll
        for (int t = 0; t < NV; t++) xd[t] = dup2(xv[t]);

        #pragma unroll
        for (int k = 0; k < K; k++) {
            const float* wr = cur + k * WSP + to;
            union { float4 f4[CPT / 4]; unsigned long long u[PAIRS]; } wu;
            #pragma unroll
            for (int t = 0; t < CPT / 4; t++)
                wu.f4[t] = *reinterpret_cast<const float4*>(wr + 4 * t);
            #pragma unroll
            for (int p = 0; p < PAIRS; p++) {
                #pragma unroll
                for (int j = 0; j < 8; j++)
                    fma2(acc[p][j], wu.u[p], xd[2 * j + k]);
            }
        }
    }

    // ---- epilogue ----
    float* on = out + (size_t)n * C * L_OUT + (size_t)(oc0 + to) * L_OUT;
    #pragma unroll
    for (int p = 0; p < PAIRS; p++) {
        const float b0 = b[oc0 + to + 2 * p];
        const float b1 = b[oc0 + to + 2 * p + 1];
        #pragma unroll
        for (int j = 0; j < 8; j++) {
            int l = l0 + tl + j;
            if (l < L_OUT) {
                float lo, hi;
                unpack2(acc[p][j], lo, hi);
                float v0 = lo + b0;
                float v1 = hi + b1;
                if (RELU) {
                    v0 = (v0 > 0.0f) ? v0 : 0.1f * v0;
                    v1 = (v1 > 0.0f) ? v1 : 0.1f * v1;
                }
                on[(2 * p) * L_OUT + l]     = v0;
                on[(2 * p + 1) * L_OUT + l] = v1;
            }
        }
    }
}

// ---------------------------------------------------------------------------
// Distance + Student-t soft assignment (alpha=1).
// ---------------------------------------------------------------------------
__global__ void __launch_bounds__(256)
dist_kernel(const float* __restrict__ z, const float* __restrict__ cen,
            float* __restrict__ q)
{
    __shared__ float zs[D];
    __shared__ float d2s[KC];
    __shared__ float qv[KC];
    __shared__ float ssum;

    const int tid = threadIdx.x;
    const int n   = blockIdx.x;

    const float* zr = z + (size_t)n * D;
    for (int idx = tid; idx < D; idx += 256) zs[idx] = zr[idx];
    __syncthreads();

    const int warp = tid >> 5;
    const int lane = tid & 31;

    #pragma unroll
    for (int cc = 0; cc < 8; cc++) {
        const int c = warp * 8 + cc;
        const float* cr = cen + (size_t)c * D;
        float s = 0.0f;
        #pragma unroll 4
        for (int idx = lane; idx < D; idx += 32) {
            float df = zs[idx] - cr[idx];
            s = fmaf(df, df, s);
        }
        #pragma unroll
        for (int off = 16; off; off >>= 1)
            s += __shfl_xor_sync(0xffffffffu, s, off);
        if (lane == 0) d2s[c] = s;
    }
    __syncthreads();

    if (tid < KC) qv[tid] = 1.0f / (1.0f + d2s[tid]);
    __syncthreads();

    if (tid < 32) {
        float s = qv[tid] + qv[tid + 32];
        #pragma unroll
        for (int off = 16; off; off >>= 1)
            s += __shfl_xor_sync(0xffffffffu, s, off);
        if (tid == 0) ssum = s;
    }
    __syncthreads();

    if (tid < KC) q[(size_t)n * KC + tid] = qv[tid] / ssum;
}

// ---------------------------------------------------------------------------
// Launch
// ---------------------------------------------------------------------------
template<int K, int OCB>
static constexpr int conv_smem_bytes() {
    constexpr int TL  = 64;
    constexpr int WX  = 2 * TL + K - 2;
    constexpr int WXP = (WX + 3) & ~3;
    constexpr int WSP = OCB + 4;
    return (C * WXP + 4 * K * WSP) * (int)sizeof(float);
}

extern "C" void kernel_launch(void* const* d_in, const int* in_sizes, int n_in,
                              void* d_out, int out_size)
{
    const float* x   = (const float*)d_in[0];
    const float* w1  = (const float*)d_in[1];
    const float* b1  = (const float*)d_in[2];
    const float* w2  = (const float*)d_in[3];
    const float* b2  = (const float*)d_in[4];
    const float* w3  = (const float*)d_in[5];
    const float* b3  = (const float*)d_in[6];
    const float* w4  = (const float*)d_in[7];
    const float* b4  = (const float*)d_in[8];
    const float* cen = (const float*)d_in[9];
    float* q = (float*)d_out;

    float* h1; cudaGetSymbolAddress((void**)&h1, g_h1);
    float* h2; cudaGetSymbolAddress((void**)&h2, g_h2);
    float* h3; cudaGetSymbolAddress((void**)&h3, g_h3);
    float* h4; cudaGetSymbolAddress((void**)&h4, g_h4);

    cudaFuncSetAttribute(conv_kernel<15, L0, L1, true, 128>,
        cudaFuncAttributeMaxDynamicSharedMemorySize, conv_smem_bytes<15, 128>());
    cudaFuncSetAttribute(conv_kernel<12, L1, L2, true, 128>,
        cudaFuncAttributeMaxDynamicSharedMemorySize, conv_smem_bytes<12, 128>());
    cudaFuncSetAttribute(conv_kernel<7,  L2, L3, true, 128>,
        cudaFuncAttributeMaxDynamicSharedMemorySize, conv_smem_bytes<7, 128>());
    cudaFuncSetAttribute(conv_kernel<4,  L3, L4, false, 64>,
        cudaFuncAttributeMaxDynamicSharedMemorySize, conv_smem_bytes<4, 64>());

    conv_kernel<15, L0, L1, true, 128><<<dim3(8, N_BATCH, 1), 128,
        conv_smem_bytes<15, 128>()>>>(x,  w1, b1, h1);
    conv_kernel<12, L1, L2, true, 128><<<dim3(4, N_BATCH, 1), 128,
        conv_smem_bytes<12, 128>()>>>(h1, w2, b2, h2);
    conv_kernel<7,  L2, L3, true, 128><<<dim3(2, N_BATCH, 1), 128,
        conv_smem_bytes<7, 128>()>>>(h2, w3, b3, h3);
    conv_kernel<4,  L3, L4, false, 64><<<dim3(1, N_BATCH, 2), 128,
        conv_smem_bytes<4, 64>()>>>(h3, w4, b4, h4);

    dist_kernel<<<N_BATCH, 256>>>(h4, cen, q);
}

// round 10
// speedup vs baseline: 4.7871x; 2.8394x over previous
#include <cuda_runtime.h>
#include <cuda_bf16.h>
#include <cstdint>
#include <cstddef>

// ---------------- problem constants ----------------
constexpr int N_BATCH = 256;
constexpr int C  = 128;
constexpr int L0 = 1024;
constexpr int L1 = 505;
constexpr int L2 = 247;
constexpr int L3 = 121;
constexpr int L4 = 59;
constexpr int D  = C * L4;     // 7552
constexpr int KC = 64;

// phase-split padded half-lengths per activation tensor
constexpr int LHP0 = 528;   // x      (Lh=512, reads reach 519)
constexpr int LHP1 = 272;   // h1     (Lh=253, reads reach 263)
constexpr int LHP2 = 144;   // h2     (Lh=124, reads reach 131)
constexpr int LHP3 = 80;    // h3     (Lh=61,  reads reach 68)
constexpr int LHP4 = 32;    // h4     (Lh=30)

// ---------------- device buffers (zero-initialized; pads stay 0) ----------
__device__ __align__(1024) float g_x0[(size_t)N_BATCH * C * 2 * LHP0];
__device__ __align__(1024) float g_h1[(size_t)N_BATCH * C * 2 * LHP1];
__device__ __align__(1024) float g_h2[(size_t)N_BATCH * C * 2 * LHP2];
__device__ __align__(1024) float g_h3[(size_t)N_BATCH * C * 2 * LHP3];
__device__ __align__(1024) float g_h4[(size_t)N_BATCH * C * 2 * LHP4];
// weights packed in mma-fragment order, tf32-rounded
__device__ __align__(1024) float g_wk[(15 + 12 + 7 + 4) * C * C];

constexpr int WOFF1 = 0;
constexpr int WOFF2 = 15 * C * C;
constexpr int WOFF3 = (15 + 12) * C * C;
constexpr int WOFF4 = (15 + 12 + 7) * C * C;

// ---------------- helpers ----------------
__device__ __forceinline__ float to_tf32(float v) {
    uint32_t r;
    asm("cvt.rna.tf32.f32 %0, %1;" : "=r"(r) : "f"(v));
    return __uint_as_float(r);
}
__device__ __forceinline__ void cp16(void* dst, const void* src) {
    unsigned d = (unsigned)__cvta_generic_to_shared(dst);
    asm volatile("cp.async.ca.shared.global [%0], [%1], 16;"
                 :: "r"(d), "l"(src) : "memory");
}
#define CP_COMMIT() asm volatile("cp.async.commit_group;" ::: "memory")
#define CP_WAIT(n)  asm volatile("cp.async.wait_group %0;" :: "n"(n) : "memory")

__device__ __forceinline__ void mma8(float* c, const uint4& a,
                                     uint32_t b0, uint32_t b1) {
    asm volatile(
        "mma.sync.aligned.m16n8k8.row.col.f32.tf32.tf32.f32 "
        "{%0,%1,%2,%3}, {%4,%5,%6,%7}, {%8,%9}, {%0,%1,%2,%3};"
        : "+f"(c[0]), "+f"(c[1]), "+f"(c[2]), "+f"(c[3])
        : "r"(a.x), "r"(a.y), "r"(a.z), "r"(a.w), "r"(b0), "r"(b1));
}

// ---------------------------------------------------------------------------
// Pre-pass 1: de-interleave x [n][c][l] -> [n][c][parity][LHP0], tf32-rounded.
// ---------------------------------------------------------------------------
__global__ void phase_split_x(const float* __restrict__ x, float* __restrict__ o) {
    size_t idx = (size_t)blockIdx.x * 256 + threadIdx.x;
    if (idx >= (size_t)N_BATCH * C * L0) return;
    int l = (int)(idx & (L0 - 1));
    size_t nc = idx >> 10;                  // n*128 + c
    o[(nc * 2 + (l & 1)) * LHP0 + (l >> 1)] = to_tf32(x[idx]);
}

// ---------------------------------------------------------------------------
// Pre-pass 2: pack W[oc][ic][k] into mma-A-fragment order, tf32-rounded.
// Chunk c2 = k*4+icq (32 ic each); within: kstep s(4), m-tile m(8), lane, 4 vals.
// a0=W[16m+g][ic0+t], a1=W[+8][..], a2=W[..][ic0+t+4], a3=W[+8][ic0+t+4]
// ---------------------------------------------------------------------------
template<int K>
__global__ void pack_w(const float* __restrict__ w, float* __restrict__ wk) {
    int i = blockIdx.x * 256 + threadIdx.x;
    if (i >= K * C * C) return;
    int i4   = i & 3;
    int lane = (i >> 2) & 31;
    int m    = (i >> 7) & 7;
    int s    = (i >> 10) & 3;
    int c2   = i >> 12;
    int k    = c2 >> 2;
    int icq  = c2 & 3;
    int oc = 16 * m + (lane >> 2) + (i4 & 1) * 8;
    int ic = icq * 32 + 8 * s + (lane & 3) + (i4 >> 1) * 4;
    wk[i] = to_tf32(w[((size_t)oc * C + ic) * K + k]);
}

// ---------------------------------------------------------------------------
// tf32 mma.sync conv layer (stride 2, VALID).
// CTA: 128 oc x (64 pos x 2 samples). 256 threads = 8 warps, warp = 32oc x 64col.
// Chunks = K taps x 4 ic-quarters; cp.async double-buffered.
// ---------------------------------------------------------------------------
template<int K, int L_OUT, int LHP_IN, int LHP_OUT, bool RELU, bool ROUND>
__global__ void __launch_bounds__(256)
conv_mma(const float* __restrict__ xin, const float* __restrict__ wpk,
         const float* __restrict__ bias, float* __restrict__ out)
{
    constexpr int NCH    = K * 4;
    constexpr int BROW   = 72;                    // B row stride (floats)
    constexpr int AFLT   = 4096;                  // A chunk floats (128oc x 32ic)
    constexpr int BFLT   = 2 * 32 * BROW;         // B chunk floats (2 samp x 32ic)
    constexpr int STAGEF = AFLT + BFLT;

    extern __shared__ float sm[];

    const int tid  = threadIdx.x;
    const int w    = tid >> 5;
    const int lane = tid & 31;
    const int wm   = w >> 1;        // M warp (32 oc)
    const int wn   = w & 1;         // sample within pair
    const int n0   = blockIdx.x * 64;
    const int n    = blockIdx.y * 2;
    const int g8   = lane >> 2;
    const int tig  = lane & 3;

    float acc[2][8][4];
    #pragma unroll
    for (int m = 0; m < 2; m++)
        #pragma unroll
        for (int t = 0; t < 8; t++)
            #pragma unroll
            for (int j = 0; j < 4; j++) acc[m][t][j] = 0.0f;

    auto stage = [&](int c2, float* buf) {
        // A: contiguous prepacked 16KB
        {
            const float4* src = (const float4*)(wpk + (size_t)c2 * AFLT);
            float4* dst = (float4*)buf;
            #pragma unroll 1
            for (int j = tid; j < AFLT / 4; j += 256) cp16(&dst[j], &src[j]);
        }
        // B: 2 samples x 32 ic rows x 17 x 16B (aligned-down window)
        {
            int k     = c2 >> 2;
            int icq   = c2 & 3;
            int phase = k & 1;
            int a0i   = (n0 + (k >> 1)) & ~3;
            float* bb = buf + AFLT;
            #pragma unroll 1
            for (int j = tid; j < 2 * 32 * 17; j += 256) {
                int s2  = j / 544;
                int r   = j - s2 * 544;
                int row = r / 17;
                int t16 = r - row * 17;
                const float* src = xin +
                    (((size_t)(n + s2) * C + icq * 32 + row) * 2 + phase) * LHP_IN
                    + a0i + t16 * 4;
                cp16(bb + (s2 * 32 + row) * BROW + t16 * 4, src);
            }
        }
    };

    stage(0, sm);           CP_COMMIT();
    stage(1, sm + STAGEF);  CP_COMMIT();

    #pragma unroll 1
    for (int c2 = 0; c2 < NCH; c2++) {
        if (c2 == NCH - 1) CP_WAIT(0); else CP_WAIT(1);
        __syncthreads();

        float* buf = sm + (c2 & 1) * STAGEF;
        const int k    = c2 >> 2;
        const int boff = (n0 + (k >> 1)) & 3;
        const float* Abuf = buf;
        const float* Bw   = buf + AFLT + (wn * 32) * BROW + boff + g8;

        #pragma unroll
        for (int s = 0; s < 4; s++) {
            uint4 a0 = *(const uint4*)(Abuf + (s * 8 + 2 * wm)     * 128 + lane * 4);
            uint4 a1 = *(const uint4*)(Abuf + (s * 8 + 2 * wm + 1) * 128 + lane * 4);
            const float* br = Bw + (8 * s + tig) * BROW;
            #pragma unroll
            for (int t = 0; t < 8; t++) {
                uint32_t b0 = __float_as_uint(br[8 * t]);
                uint32_t b1 = __float_as_uint(br[4 * BROW + 8 * t]);
                mma8(acc[0][t], a0, b0, b1);
                mma8(acc[1][t], a1, b0, b1);
            }
        }
        __syncthreads();
        if (c2 + 2 < NCH) { stage(c2 + 2, buf); CP_COMMIT(); }
    }

    // ---- epilogue: bias + LeakyReLU (+tf32 round) -> [n][c][parity][LHP_OUT]
    const int nn = n + wn;
    #pragma unroll
    for (int m = 0; m < 2; m++) {
        const int oc0 = wm * 32 + m * 16 + g8;
        const int oc1 = oc0 + 8;
        const float bv0 = bias[oc0];
        const float bv1 = bias[oc1];
        float* o0 = out + (((size_t)nn * C + oc0) * 2) * LHP_OUT;
        float* o1 = out + (((size_t)nn * C + oc1) * 2) * LHP_OUT;
        #pragma unroll
        for (int t = 0; t < 8; t++) {
            const int pos = n0 + 8 * t + 2 * tig;
            const int idx = pos >> 1;
            #pragma unroll
            for (int r = 0; r < 4; r++) {
                const int p  = pos + (r & 1);
                if (p >= L_OUT) continue;
                float v = acc[m][t][r] + ((r < 2) ? bv0 : bv1);
                if (RELU)  v = (v > 0.0f) ? v : 0.1f * v;
                if (ROUND) v = to_tf32(v);
                float* ob = (r < 2) ? o0 : o1;
                ob[(r & 1) * LHP_OUT + idx] = v;
            }
        }
    }
}

// ---------------------------------------------------------------------------
// Distance + Student-t soft assignment (alpha=1).
// Gathers z from phase-split h4 into original (c*L4+l) order; centers as-is.
// ---------------------------------------------------------------------------
__global__ void __launch_bounds__(256)
dist_kernel(const float* __restrict__ z, const float* __restrict__ cen,
            float* __restrict__ q)
{
    __shared__ float zs[D];
    __shared__ float d2s[KC];
    __shared__ float qv[KC];
    __shared__ float ssum;

    const int tid = threadIdx.x;
    const int n   = blockIdx.x;

    const float* zr = z + (size_t)n * C * 2 * LHP4;
    for (int j = tid; j < D; j += 256) {
        int c = j / L4;
        int l = j - c * L4;
        zs[j] = zr[(c * 2 + (l & 1)) * LHP4 + (l >> 1)];
    }
    __syncthreads();

    const int warp = tid >> 5;
    const int lane = tid & 31;

    #pragma unroll
    for (int cc = 0; cc < 8; cc++) {
        const int c = warp * 8 + cc;
        const float* cr = cen + (size_t)c * D;
        float s = 0.0f;
        #pragma unroll 4
        for (int idx = lane; idx < D; idx += 32) {
            float df = zs[idx] - cr[idx];
            s = fmaf(df, df, s);
        }
        #pragma unroll
        for (int off = 16; off; off >>= 1)
            s += __shfl_xor_sync(0xffffffffu, s, off);
        if (lane == 0) d2s[c] = s;
    }
    __syncthreads();

    if (tid < KC) qv[tid] = 1.0f / (1.0f + d2s[tid]);
    __syncthreads();

    if (tid < 32) {
        float s = qv[tid] + qv[tid + 32];
        #pragma unroll
        for (int off = 16; off; off >>= 1)
            s += __shfl_xor_sync(0xffffffffu, s, off);
        if (tid == 0) ssum = s;
    }
    __syncthreads();

    if (tid < KC) q[(size_t)n * KC + tid] = qv[tid] / ssum;
}

// ---------------------------------------------------------------------------
// Host side
// ---------------------------------------------------------------------------
constexpr int CONV_SMEM = 2 * (4096 + 2 * 32 * 72) * (int)sizeof(float); // 69632

extern "C" void kernel_launch(void* const* d_in, const int* in_sizes, int n_in,
                              void* d_out, int out_size)
{
    const float* x   = (const float*)d_in[0];
    const float* w1  = (const float*)d_in[1];
    const float* b1  = (const float*)d_in[2];
    const float* w2  = (const float*)d_in[3];
    const float* b2  = (const float*)d_in[4];
    const float* w3  = (const float*)d_in[5];
    const float* b3  = (const float*)d_in[6];
    const float* w4  = (const float*)d_in[7];
    const float* b4  = (const float*)d_in[8];
    const float* cen = (const float*)d_in[9];
    float* q = (float*)d_out;

    float* x0; cudaGetSymbolAddress((void**)&x0, g_x0);
    float* h1; cudaGetSymbolAddress((void**)&h1, g_h1);
    float* h2; cudaGetSymbolAddress((void**)&h2, g_h2);
    float* h3; cudaGetSymbolAddress((void**)&h3, g_h3);
    float* h4; cudaGetSymbolAddress((void**)&h4, g_h4);
    float* wk; cudaGetSymbolAddress((void**)&wk, g_wk);

    cudaFuncSetAttribute(conv_mma<15, L1, LHP0, LHP1, true,  true>,
        cudaFuncAttributeMaxDynamicSharedMemorySize, CONV_SMEM);
    cudaFuncSetAttribute(conv_mma<12, L2, LHP1, LHP2, true,  true>,
        cudaFuncAttributeMaxDynamicSharedMemorySize, CONV_SMEM);
    cudaFuncSetAttribute(conv_mma<7,  L3, LHP2, LHP3, true,  true>,
        cudaFuncAttributeMaxDynamicSharedMemorySize, CONV_SMEM);
    cudaFuncSetAttribute(conv_mma<4,  L4, LHP3, LHP4, false, false>,
        cudaFuncAttributeMaxDynamicSharedMemorySize, CONV_SMEM);

    // pre-passes
    {
        size_t tot = (size_t)N_BATCH * C * L0;
        phase_split_x<<<(unsigned)((tot + 255) / 256), 256>>>(x, x0);
    }
    pack_w<15><<<(15 * C * C + 255) / 256, 256>>>(w1, wk + WOFF1);
    pack_w<12><<<(12 * C * C + 255) / 256, 256>>>(w2, wk + WOFF2);
    pack_w<7> <<<(7  * C * C + 255) / 256, 256>>>(w3, wk + WOFF3);
    pack_w<4> <<<(4  * C * C + 255) / 256, 256>>>(w4, wk + WOFF4);

    // conv stack (tensor-core tf32 mma.sync)
    conv_mma<15, L1, LHP0, LHP1, true,  true><<<dim3(8, N_BATCH / 2), 256, CONV_SMEM>>>(
        x0, wk + WOFF1, b1, h1);
    conv_mma<12, L2, LHP1, LHP2, true,  true><<<dim3(4, N_BATCH / 2), 256, CONV_SMEM>>>(
        h1, wk + WOFF2, b2, h2);
    conv_mma<7,  L3, LHP2, LHP3, true,  true><<<dim3(2, N_BATCH / 2), 256, CONV_SMEM>>>(
        h2, wk + WOFF3, b3, h3);
    conv_mma<4,  L4, LHP3, LHP4, false, false><<<dim3(1, N_BATCH / 2), 256, CONV_SMEM>>>(
        h3, wk + WOFF4, b4, h4);

    dist_kernel<<<N_BATCH, 256>>>(h4, cen, q);
}

// round 14
// speedup vs baseline: 9.0819x; 1.8971x over previous
#include <cuda_runtime.h>
#include <cuda_fp16.h>
#include <cstdint>
#include <cstddef>

// ---------------- problem constants ----------------
constexpr int N_BATCH = 256;
constexpr int C  = 128;
constexpr int L0 = 1024;
constexpr int L1 = 505;
constexpr int L2 = 247;
constexpr int L3 = 121;
constexpr int L4 = 59;
constexpr int D  = C * L4;     // 7552
constexpr int KC = 64;

// padded sequence lengths (rows beyond L stay zero from static init; conv reads
// of pad rows contribute 0). LP_IN must cover 2*(p0+MT-1)+K-1.
constexpr int LP0 = 1040;   // conv1 reads to 2*511+14 = 1036
constexpr int LP1 = 528;    // conv2 reads to 2*255+11 = 521
constexpr int LP2 = 264;    // conv3 reads to 2*127+6  = 260
constexpr int LP3 = 136;    // conv4 reads to 2*63+3   = 129
constexpr int LP4 = 64;     // h4 (59 valid)

// ---------------- device buffers (zero-initialized; pads stay 0) ----------
__device__ __align__(1024) __half g_x [(size_t)N_BATCH * LP0 * C];
__device__ __align__(1024) __half g_h1[(size_t)N_BATCH * LP1 * C];
__device__ __align__(1024) __half g_h2[(size_t)N_BATCH * LP2 * C];
__device__ __align__(1024) __half g_h3[(size_t)N_BATCH * LP3 * C];
__device__ __align__(1024) __half g_h4[(size_t)N_BATCH * LP4 * C];
// weights prepacked into exact m16n8k16 B-fragment order (half)
__device__ __align__(1024) __half g_wk[(15 + 12 + 7 + 4) * C * C];

constexpr int WOFF1 = 0;
constexpr int WOFF2 = 15 * C * C;
constexpr int WOFF3 = (15 + 12) * C * C;
constexpr int WOFF4 = (15 + 12 + 7) * C * C;

// ---------------- helpers ----------------
__device__ __forceinline__ uint32_t smem_u32(const void* p) {
    uint32_t a;
    asm("{ .reg .u64 t; cvta.to.shared.u64 t, %1; cvt.u32.u64 %0, t; }"
        : "=r"(a) : "l"(p));
    return a;
}
__device__ __forceinline__ void cp16(void* dst, const void* src) {
    unsigned d = (unsigned)__cvta_generic_to_shared(dst);
    asm volatile("cp.async.ca.shared.global [%0], [%1], 16;"
                 :: "r"(d), "l"(src) : "memory");
}
#define CP_COMMIT() asm volatile("cp.async.commit_group;" ::: "memory")
#define CP_WAIT(n)  asm volatile("cp.async.wait_group %0;" :: "n"(n) : "memory")

__device__ __forceinline__ void ldsm4(uint32_t* a, uint32_t addr) {
    asm volatile("ldmatrix.sync.aligned.m8n8.x4.shared.b16 {%0,%1,%2,%3}, [%4];"
                 : "=r"(a[0]), "=r"(a[1]), "=r"(a[2]), "=r"(a[3]) : "r"(addr));
}
// D[m16=pos][n8=oc] += A[m16][k16=ic] * B[k16][n8]; fp16 in, fp32 accum
__device__ __forceinline__ void mma16(float* c, const uint32_t* a,
                                      uint32_t b0, uint32_t b1) {
    asm volatile(
        "mma.sync.aligned.m16n8k16.row.col.f32.f16.f16.f32 "
        "{%0,%1,%2,%3}, {%4,%5,%6,%7}, {%8,%9}, {%0,%1,%2,%3};"
        : "+f"(c[0]), "+f"(c[1]), "+f"(c[2]), "+f"(c[3])
        : "r"(a[0]), "r"(a[1]), "r"(a[2]), "r"(a[3]), "r"(b0), "r"(b1));
}

// ---------------------------------------------------------------------------
// Pre-pass 1: x [n][c][l] fp32 -> [n][l(pad)][c] half
// ---------------------------------------------------------------------------
__global__ void transpose_x(const float* __restrict__ x, __half* __restrict__ o) {
    __shared__ float t[32][33];
    int n = blockIdx.z, c0 = blockIdx.y * 32, l0 = blockIdx.x * 32;
    int tx = threadIdx.x, ty = threadIdx.y;
    #pragma unroll
    for (int i = 0; i < 4; i++)
        t[ty + 8 * i][tx] = x[((size_t)n * C + c0 + ty + 8 * i) * L0 + l0 + tx];
    __syncthreads();
    #pragma unroll
    for (int i = 0; i < 4; i++)
        o[((size_t)n * LP0 + l0 + ty + 8 * i) * C + c0 + tx] =
            __float2half(t[tx][ty + 8 * i]);
}

// ---------------------------------------------------------------------------
// Pre-pass 2: W[oc][ic][k] -> m16n8k16 B-fragment order, half.
// Linear layout: [c2 = k*2+ich][s(4)][ntq(8)][lane(32)][8 halves], where the
// 8 halves are {b0lo,b0hi,b1lo,b1hi}@nt=2ntq then same @nt=2ntq+1.
// b0 = B[k16: 2tig..2tig+1][oc: nt*8+g8], b1 = B[2tig+8..2tig+9][same oc].
// ---------------------------------------------------------------------------
template<int K>
__global__ void pack_w(const float* __restrict__ w, __half* __restrict__ wk) {
    int i = blockIdx.x * 256 + threadIdx.x;
    if (i >= K * C * C) return;
    int c2   = i >> 13;
    int r    = i & 8191;
    int s    = r >> 11;
    int r2   = r & 2047;
    int ntq  = r2 >> 8;
    int r3   = r2 & 255;
    int lane = r3 >> 3;
    int h    = r3 & 7;
    int nt   = ntq * 2 + (h >> 2);
    int hh   = h & 3;
    int breg = hh >> 1;
    int ic_in = 16 * s + 2 * (lane & 3) + (hh & 1) + breg * 8;
    int oc    = nt * 8 + (lane >> 2);
    int k     = c2 >> 1;
    int ic    = (c2 & 1) * 64 + ic_in;
    wk[i] = __float2half(w[((size_t)oc * C + ic) * K + k]);
}

// ---------------------------------------------------------------------------
// fp16 mma conv layer (stride 2, VALID).
// CTA: MT output positions x 128 oc, one sample. 256 threads = 8 warps.
// warp = (MT/4) pos x 64 oc. Chunks = (tap k, ic-half): A tile = activations
// [MT pos][64 ic] staged with stride-2 row gather; B = prepacked weight frags.
// ---------------------------------------------------------------------------
template<int K, int L_OUT, int LP_IN, int LP_OUT, int MT, bool RELU>
__global__ void __launch_bounds__(256)
conv_mma(const __half* __restrict__ xin, const __half* __restrict__ wpk,
         const float* __restrict__ bias, __half* __restrict__ out)
{
    constexpr int NCH    = 2 * K;
    constexpr int ABYTES = MT * 144;         // [MT][72 halves] (64 valid + pad)
    constexpr int SBYTES = ABYTES + 16384;   // + B frags (64ic x 128oc half)
    constexpr int WM     = MT / 4;           // warp M extent (pos)
    constexpr int NMT    = WM / 16;          // m16 tiles per warp

    extern __shared__ __align__(16) char sm[];

    const int tid  = threadIdx.x;
    const int w    = tid >> 5;
    const int lane = tid & 31;
    const int wm   = w >> 1;        // 0..3
    const int wn   = w & 1;         // oc half
    const int g8   = lane >> 2;
    const int tig  = lane & 3;
    const int n    = blockIdx.y;
    const int p0   = blockIdx.x * MT;

    float acc[NMT][8][4];
    #pragma unroll
    for (int m = 0; m < NMT; m++)
        #pragma unroll
        for (int j = 0; j < 8; j++)
            #pragma unroll
            for (int r = 0; r < 4; r++) acc[m][j][r] = 0.0f;

    auto stage = [&](int c2, char* buf) {
        const int k   = c2 >> 1;
        const int ich = c2 & 1;
        const __half* asrc = xin + ((size_t)n * LP_IN + k) * C + ich * 64;
        #pragma unroll 1
        for (int j = tid; j < MT * 8; j += 256) {
            int row = j >> 3, t = j & 7;
            cp16(buf + row * 144 + t * 16, asrc + (size_t)2 * (p0 + row) * C + t * 8);
        }
        const __half* bsrc = wpk + (size_t)c2 * 8192;
        #pragma unroll 1
        for (int j = tid; j < 1024; j += 256)
            cp16(buf + ABYTES + j * 16, bsrc + j * 8);
    };

    stage(0, sm);           CP_COMMIT();
    stage(1, sm + SBYTES);  CP_COMMIT();

    #pragma unroll 1
    for (int c2 = 0; c2 < NCH; c2++) {
        if (c2 == NCH - 1) CP_WAIT(0); else CP_WAIT(1);
        __syncthreads();

        char* buf = sm + (c2 & 1) * SBYTES;
        const uint32_t abase = smem_u32(buf);

        #pragma unroll
        for (int s = 0; s < 4; s++) {
            uint32_t a[NMT][4];
            #pragma unroll
            for (int m = 0; m < NMT; m++) {
                uint32_t addr = abase
                    + (uint32_t)(wm * WM + m * 16 + (lane & 15)) * 144
                    + s * 32 + (lane >> 4) * 16;
                ldsm4(a[m], addr);
            }
            #pragma unroll
            for (int qq = 0; qq < 4; qq++) {
                uint4 bv = *(const uint4*)(buf + ABYTES
                    + ((size_t)((s * 8 + wn * 4 + qq) * 32 + lane)) * 16);
                #pragma unroll
                for (int m = 0; m < NMT; m++) {
                    mma16(acc[m][2 * qq],     a[m], bv.x, bv.y);
                    mma16(acc[m][2 * qq + 1], a[m], bv.z, bv.w);
                }
            }
        }
        __syncthreads();
        if (c2 + 2 < NCH) { stage(c2 + 2, buf); CP_COMMIT(); }
    }

    // ---- epilogue: bias + LeakyReLU, half2 (oc-pair) stores to [n][pos][c]
    float bv0[8], bv1[8];
    #pragma unroll
    for (int j = 0; j < 8; j++) {
        int oc = (8 * wn + j) * 8 + 2 * tig;
        bv0[j] = bias[oc];
        bv1[j] = bias[oc + 1];
    }
    #pragma unroll
    for (int m = 0; m < NMT; m++) {
        const int pb = p0 + wm * WM + m * 16 + g8;
        #pragma unroll
        for (int j = 0; j < 8; j++) {
            const int oc = (8 * wn + j) * 8 + 2 * tig;
            #pragma unroll
            for (int r = 0; r < 2; r++) {
                const int pos = pb + 8 * r;
                if (pos < L_OUT) {
                    float v0 = acc[m][j][2 * r]     + bv0[j];
                    float v1 = acc[m][j][2 * r + 1] + bv1[j];
                    if (RELU) {
                        v0 = (v0 > 0.0f) ? v0 : 0.1f * v0;
                        v1 = (v1 > 0.0f) ? v1 : 0.1f * v1;
                    }
                    *(__half2*)(out + ((size_t)n * LP_OUT + pos) * C + oc) =
                        __floats2half2_rn(v0, v1);
                }
            }
        }
    }
}

// ---------------------------------------------------------------------------
// Distance + Student-t soft assignment (alpha=1). z gathered from half
// [n][l(pad)][c] layout back to (c*L4+l) order to match centers.
// ---------------------------------------------------------------------------
__global__ void __launch_bounds__(256)
dist_kernel(const __half* __restrict__ z, const float* __restrict__ cen,
            float* __restrict__ q)
{
    __shared__ float zs[D];
    __shared__ float d2s[KC];
    __shared__ float qv[KC];
    __shared__ float ssum;

    const int tid = threadIdx.x;
    const int n   = blockIdx.x;

    const __half* zr = z + (size_t)n * LP4 * C;
    for (int j = tid; j < D; j += 256) {
        int l = j >> 7;
        int c = j & 127;
        zs[c * L4 + l] = __half2float(zr[l * C + c]);
    }
    __syncthreads();

    const int warp = tid >> 5;
    const int lane = tid & 31;

    #pragma unroll
    for (int cc = 0; cc < 8; cc++) {
        const int c = warp * 8 + cc;
        const float* cr = cen + (size_t)c * D;
        float s = 0.0f;
        #pragma unroll 4
        for (int idx = lane; idx < D; idx += 32) {
            float df = zs[idx] - cr[idx];
            s = fmaf(df, df, s);
        }
        #pragma unroll
        for (int off = 16; off; off >>= 1)
            s += __shfl_xor_sync(0xffffffffu, s, off);
        if (lane == 0) d2s[c] = s;
    }
    __syncthreads();

    if (tid < KC) qv[tid] = 1.0f / (1.0f + d2s[tid]);
    __syncthreads();

    if (tid < 32) {
        float s = qv[tid] + qv[tid + 32];
        #pragma unroll
        for (int off = 16; off; off >>= 1)
            s += __shfl_xor_sync(0xffffffffu, s, off);
        if (tid == 0) ssum = s;
    }
    __syncthreads();

    if (tid < KC) q[(size_t)n * KC + tid] = qv[tid] / ssum;
}

// ---------------------------------------------------------------------------
// Host side
// ---------------------------------------------------------------------------
template<int MT>
static constexpr int conv_smem() { return 2 * (MT * 144 + 16384); }

extern "C" void kernel_launch(void* const* d_in, const int* in_sizes, int n_in,
                              void* d_out, int out_size)
{
    const float* x   = (const float*)d_in[0];
    const float* w1  = (const float*)d_in[1];
    const float* b1  = (const float*)d_in[2];
    const float* w2  = (const float*)d_in[3];
    const float* b2  = (const float*)d_in[4];
    const float* w3  = (const float*)d_in[5];
    const float* b3  = (const float*)d_in[6];
    const float* w4  = (const float*)d_in[7];
    const float* b4  = (const float*)d_in[8];
    const float* cen = (const float*)d_in[9];
    float* q = (float*)d_out;

    __half* xh; cudaGetSymbolAddress((void**)&xh, g_x);
    __half* h1; cudaGetSymbolAddress((void**)&h1, g_h1);
    __half* h2; cudaGetSymbolAddress((void**)&h2, g_h2);
    __half* h3; cudaGetSymbolAddress((void**)&h3, g_h3);
    __half* h4; cudaGetSymbolAddress((void**)&h4, g_h4);
    __half* wk; cudaGetSymbolAddress((void**)&wk, g_wk);

    cudaFuncSetAttribute(conv_mma<15, L1, LP0, LP1, 128, true>,
        cudaFuncAttributeMaxDynamicSharedMemorySize, conv_smem<128>());
    cudaFuncSetAttribute(conv_mma<12, L2, LP1, LP2, 128, true>,
        cudaFuncAttributeMaxDynamicSharedMemorySize, conv_smem<128>());
    cudaFuncSetAttribute(conv_mma<7,  L3, LP2, LP3, 128, true>,
        cudaFuncAttributeMaxDynamicSharedMemorySize, conv_smem<128>());
    cudaFuncSetAttribute(conv_mma<4,  L4, LP3, LP4, 64,  false>,
        cudaFuncAttributeMaxDynamicSharedMemorySize, conv_smem<64>());

    // pre-passes
    transpose_x<<<dim3(L0 / 32, C / 32, N_BATCH), dim3(32, 8)>>>(x, xh);
    pack_w<15><<<(15 * C * C + 255) / 256, 256>>>(w1, wk + WOFF1);
    pack_w<12><<<(12 * C * C + 255) / 256, 256>>>(w2, wk + WOFF2);
    pack_w<7> <<<(7  * C * C + 255) / 256, 256>>>(w3, wk + WOFF3);
    pack_w<4> <<<(4  * C * C + 255) / 256, 256>>>(w4, wk + WOFF4);

    // conv stack (fp16 tensor-core mma, fp32 accumulate)
    conv_mma<15, L1, LP0, LP1, 128, true><<<dim3(4, N_BATCH), 256, conv_smem<128>()>>>(
        xh, wk + WOFF1, b1, h1);
    conv_mma<12, L2, LP1, LP2, 128, true><<<dim3(2, N_BATCH), 256, conv_smem<128>()>>>(
        h1, wk + WOFF2, b2, h2);
    conv_mma<7,  L3, LP2, LP3, 128, true><<<dim3(1, N_BATCH), 256, conv_smem<128>()>>>(
        h2, wk + WOFF3, b3, h3);
    conv_mma<4,  L4, LP3, LP4, 64,  false><<<dim3(1, N_BATCH), 256, conv_smem<64>()>>>(
        h3, wk + WOFF4, b4, h4);

    dist_kernel<<<N_BATCH, 256>>>(h4, cen, q);
}

// round 15
// speedup vs baseline: 10.0016x; 1.1013x over previous
#include <cuda_runtime.h>
#include <cuda_fp16.h>
#include <cstdint>
#include <cstddef>

// ---------------- problem constants ----------------
constexpr int N_BATCH = 256;
constexpr int C  = 128;
constexpr int L0 = 1024;
constexpr int L1 = 505;
constexpr int L2 = 247;
constexpr int L3 = 121;
constexpr int L4 = 59;
constexpr int D  = C * L4;     // 7552
constexpr int KC = 64;

// padded sequence lengths (rows >= L stay zero forever: epilogues never write them)
constexpr int LP0 = 1040;   // conv1 window reads to 2*448+141 = 1037
constexpr int LP1 = 528;    // conv2 reads to 2*192+138 = 522
constexpr int LP2 = 264;    // conv3 reads to 2*64+133 = 261
constexpr int LP3 = 136;    // conv4 reads to 130
constexpr int LP4 = 64;     // h4 (59 valid -> first 15104B contiguous = z row)

// ---------------- device buffers (zero-initialized; pads stay 0) ----------
__device__ __align__(1024) __half g_x [(size_t)N_BATCH * LP0 * C];
__device__ __align__(1024) __half g_h1[(size_t)N_BATCH * LP1 * C];
__device__ __align__(1024) __half g_h2[(size_t)N_BATCH * LP2 * C];
__device__ __align__(1024) __half g_h3[(size_t)N_BATCH * LP3 * C];
__device__ __align__(1024) __half g_h4[(size_t)N_BATCH * LP4 * C];
// weights prepacked: per tap k, [s(8)][ntq(8)][lane(32)][8 halves] = 16384 halves
__device__ __align__(1024) __half g_wk[(15 + 12 + 7 + 4) * 16384];
// centers as half, permuted to [j][l*128+c] to match h4 layout
__device__ __align__(1024) __half g_cenh[(size_t)KC * D];

constexpr int WKB1 = 0;           // k-block offsets (units of 16384 halves)
constexpr int WKB2 = 15;
constexpr int WKB3 = 27;
constexpr int WKB4 = 34;
constexpr int W_ELEMS = 38 * 16384;   // 622592

// ---------------- helpers ----------------
__device__ __forceinline__ uint32_t smem_u32(const void* p) {
    uint32_t a;
    asm("{ .reg .u64 t; cvta.to.shared.u64 t, %1; cvt.u32.u64 %0, t; }"
        : "=r"(a) : "l"(p));
    return a;
}
__device__ __forceinline__ void cp16(void* dst, const void* src) {
    unsigned d = (unsigned)__cvta_generic_to_shared(dst);
    asm volatile("cp.async.ca.shared.global [%0], [%1], 16;"
                 :: "r"(d), "l"(src) : "memory");
}
#define CP_COMMIT() asm volatile("cp.async.commit_group;" ::: "memory")
#define CP_WAIT(n)  asm volatile("cp.async.wait_group %0;" :: "n"(n) : "memory")

__device__ __forceinline__ void ldsm4(uint32_t* a, uint32_t addr) {
    asm volatile("ldmatrix.sync.aligned.m8n8.x4.shared.b16 {%0,%1,%2,%3}, [%4];"
                 : "=r"(a[0]), "=r"(a[1]), "=r"(a[2]), "=r"(a[3]) : "r"(addr));
}
__device__ __forceinline__ void mma16(float* c, const uint32_t* a,
                                      uint32_t b0, uint32_t b1) {
    asm volatile(
        "mma.sync.aligned.m16n8k16.row.col.f32.f16.f16.f32 "
        "{%0,%1,%2,%3}, {%4,%5,%6,%7}, {%8,%9}, {%0,%1,%2,%3};"
        : "+f"(c[0]), "+f"(c[1]), "+f"(c[2]), "+f"(c[3])
        : "r"(a[0]), "r"(a[1]), "r"(a[2]), "r"(a[3]), "r"(b0), "r"(b1));
}

// ---------------------------------------------------------------------------
// Pre-pass 1: x [n][c][l] fp32 -> [n][l(pad)][c] half
// ---------------------------------------------------------------------------
__global__ void transpose_x(const float* __restrict__ x, __half* __restrict__ o) {
    __shared__ float t[32][33];
    int n = blockIdx.z, c0 = blockIdx.y * 32, l0 = blockIdx.x * 32;
    int tx = threadIdx.x, ty = threadIdx.y;
    #pragma unroll
    for (int i = 0; i < 4; i++)
        t[ty + 8 * i][tx] = x[((size_t)n * C + c0 + ty + 8 * i) * L0 + l0 + tx];
    __syncthreads();
    #pragma unroll
    for (int i = 0; i < 4; i++)
        o[((size_t)n * LP0 + l0 + ty + 8 * i) * C + c0 + tx] =
            __float2half(t[tx][ty + 8 * i]);
}

// ---------------------------------------------------------------------------
// Pre-pass 2 (fused): pack all weights into per-tap B-fragment order + centers
// to half. B-frag map (validated R14): per (s, ntq, lane, h):
//   nt = 2*ntq + (h>>2); hh = h&3; ic = 16*s + 2*(lane&3) + (hh&1) + 8*(hh>>1);
//   oc = nt*8 + (lane>>2)
// ---------------------------------------------------------------------------
__global__ void pack_all(const float* __restrict__ w1, const float* __restrict__ w2,
                         const float* __restrict__ w3, const float* __restrict__ w4,
                         const float* __restrict__ cen,
                         __half* __restrict__ wk, __half* __restrict__ cenh)
{
    int i = blockIdx.x * 256 + threadIdx.x;
    if (i < W_ELEMS) {
        int kb = i >> 14;
        int r  = i & 16383;
        const float* w; int k, K;
        if      (kb < WKB2) { w = w1; k = kb;        K = 15; }
        else if (kb < WKB3) { w = w2; k = kb - WKB2; K = 12; }
        else if (kb < WKB4) { w = w3; k = kb - WKB3; K = 7;  }
        else                { w = w4; k = kb - WKB4; K = 4;  }
        int s    = r >> 11;
        int ntq  = (r >> 8) & 7;
        int lane = (r >> 3) & 31;
        int h    = r & 7;
        int nt   = 2 * ntq + (h >> 2);
        int hh   = h & 3;
        int ic   = 16 * s + 2 * (lane & 3) + (hh & 1) + 8 * (hh >> 1);
        int oc   = nt * 8 + (lane >> 2);
        wk[i] = __float2half(w[((size_t)oc * C + ic) * K + k]);
    } else {
        int j = i - W_ELEMS;
        if (j >= KC * D) return;
        int jc = j / D;
        int r  = j - jc * D;
        int l  = r >> 7;
        int c  = r & 127;
        cenh[j] = __float2half(cen[(size_t)jc * D + c * L4 + l]);
    }
}

// ---------------------------------------------------------------------------
// fp16 mma conv (stride 2, VALID). CTA: MT=64 pos x 128 oc, one sample.
// A window (2*MT+K-1 rows x 128 ic) resident in SMEM, XOR-swizzled for
// conflict-free stride-2 ldmatrix. Tap loop with B (32KB/tap) double-buffered.
// 8 warps = 2(M: 32 pos) x 4(N: 32 oc).
// ---------------------------------------------------------------------------
template<int K, int L_OUT, int LP_IN, int LP_OUT, bool RELU>
__global__ void __launch_bounds__(256)
conv_mma(const __half* __restrict__ xin, const __half* __restrict__ wpk,
         const float* __restrict__ bias, __half* __restrict__ out)
{
    constexpr int MT     = 64;
    constexpr int WR     = 2 * MT + K - 1;    // window rows
    constexpr int ABYTES = WR * 256;          // [WR][128 ic halves] swizzled
    constexpr int BBYTES = 32768;             // one tap: 128ic x 128oc half

    extern __shared__ __align__(16) char sm[];
    char* bbuf[2] = { sm + ABYTES, sm + ABYTES + BBYTES };

    const int tid  = threadIdx.x;
    const int w    = tid >> 5;
    const int lane = tid & 31;
    const int wm   = w & 1;         // M half (32 pos)
    const int wn   = w >> 1;        // N quarter (32 oc)
    const int g8   = lane >> 2;
    const int tig  = lane & 3;
    const int n    = blockIdx.y;
    const int p0   = blockIdx.x * MT;

    float acc[2][4][4];
    #pragma unroll
    for (int m = 0; m < 2; m++)
        #pragma unroll
        for (int jn = 0; jn < 4; jn++)
            #pragma unroll
            for (int r = 0; r < 4; r++) acc[m][jn][r] = 0.0f;

    // ---- stage A window once (swizzled) ----
    {
        const __half* asrc = xin + ((size_t)n * LP_IN + 2 * p0) * C;
        #pragma unroll 1
        for (int j = tid; j < WR * 16; j += 256) {
            int r = j >> 4, t = j & 15;
            int ts = t ^ ((r >> 1) & 7);
            cp16(sm + r * 256 + ts * 16, asrc + (size_t)r * C + t * 8);
        }
    }
    CP_COMMIT();

    auto stageB = [&](int k, char* buf) {
        const __half* bsrc = wpk + (size_t)k * 16384;
        #pragma unroll 1
        for (int j = tid; j < 2048; j += 256)
            cp16(buf + j * 16, bsrc + j * 8);
    };
    stageB(0, bbuf[0]); CP_COMMIT();
    stageB(1, bbuf[1]); CP_COMMIT();
    CP_WAIT(1);             // A + B0 landed
    __syncthreads();

    const uint32_t abase = smem_u32(sm);

    #pragma unroll 1
    for (int k = 0; k < K; k++) {
        const char* bb = bbuf[k & 1];
        #pragma unroll
        for (int s = 0; s < 8; s++) {
            uint32_t a[2][4];
            #pragma unroll
            for (int m = 0; m < 2; m++) {
                int rw = 2 * (wm * 32 + m * 16 + (lane & 15)) + k;
                int ch = (s * 2 + (lane >> 4)) ^ ((rw >> 1) & 7);
                ldsm4(a[m], abase + (uint32_t)rw * 256 + (uint32_t)ch * 16);
            }
            #pragma unroll
            for (int q = 0; q < 2; q++) {
                uint4 bv = *(const uint4*)(bb +
                    ((size_t)((s * 8 + 2 * wn + q) * 32 + lane)) * 16);
                #pragma unroll
                for (int m = 0; m < 2; m++) {
                    mma16(acc[m][2 * q],     a[m], bv.x, bv.y);
                    mma16(acc[m][2 * q + 1], a[m], bv.z, bv.w);
                }
            }
        }
        __syncthreads();                       // done reading bbuf[k&1]
        if (k + 2 < K) {
            stageB(k + 2, bbuf[k & 1]); CP_COMMIT();
            CP_WAIT(1); __syncthreads();       // B[k+1] ready
        } else if (k + 1 < K) {
            CP_WAIT(0); __syncthreads();       // last B ready
        }
    }

    // ---- epilogue: bias + LeakyReLU, half2 (oc-pair) stores to [n][pos][c]
    float bv0[4], bv1[4];
    #pragma unroll
    for (int jn = 0; jn < 4; jn++) {
        int oc = (wn * 4 + jn) * 8 + 2 * tig;
        bv0[jn] = bias[oc];
        bv1[jn] = bias[oc + 1];
    }
    #pragma unroll
    for (int m = 0; m < 2; m++) {
        #pragma unroll
        for (int jn = 0; jn < 4; jn++) {
            const int oc = (wn * 4 + jn) * 8 + 2 * tig;
            #pragma unroll
            for (int r = 0; r < 2; r++) {
                const int pos = p0 + wm * 32 + m * 16 + g8 + 8 * r;
                if (pos < L_OUT) {
                    float v0 = acc[m][jn][2 * r]     + bv0[jn];
                    float v1 = acc[m][jn][2 * r + 1] + bv1[jn];
                    if (RELU) {
                        v0 = (v0 > 0.0f) ? v0 : 0.1f * v0;
                        v1 = (v1 > 0.0f) ? v1 : 0.1f * v1;
                    }
                    *(__half2*)(out + ((size_t)n * LP_OUT + pos) * C + oc) =
                        __floats2half2_rn(v0, v1);
                }
            }
        }
    }
}

// ---------------------------------------------------------------------------
// Distance + Student-t soft assignment (alpha=1). NS=2 samples per CTA,
// half z (direct contiguous copy from h4) + half centers (prepermuted).
// ---------------------------------------------------------------------------
constexpr int NS = 2;

__global__ void __launch_bounds__(256)
dist_kernel(const __half* __restrict__ z, const __half* __restrict__ cenh,
            float* __restrict__ q)
{
    extern __shared__ __align__(16) __half zh[];   // [NS][D]
    __shared__ float d2s[KC][NS];
    __shared__ float qv[NS][KC];
    __shared__ float ssum[NS];

    const int tid = threadIdx.x;
    const int n0  = blockIdx.x * NS;

    #pragma unroll
    for (int ns = 0; ns < NS; ns++) {
        const uint4* src = (const uint4*)(z + (size_t)(n0 + ns) * LP4 * C);
        uint4* dst = (uint4*)(zh + ns * D);
        for (int j = tid; j < D / 8; j += 256) dst[j] = src[j];
    }
    __syncthreads();

    const int warp = tid >> 5;
    const int lane = tid & 31;

    #pragma unroll
    for (int cc = 0; cc < 8; cc++) {
        const int c = warp * 8 + cc;
        const __half2* cr = (const __half2*)(cenh + (size_t)c * D);
        const __half2* z0 = (const __half2*)zh;
        const __half2* z1 = (const __half2*)(zh + D);
        float s0 = 0.0f, s1 = 0.0f;
        #pragma unroll 4
        for (int idx = lane; idx < D / 2; idx += 32) {
            float2 cf = __half22float2(cr[idx]);
            float2 a0 = __half22float2(z0[idx]);
            float2 a1 = __half22float2(z1[idx]);
            float d00 = a0.x - cf.x, d01 = a0.y - cf.y;
            float d10 = a1.x - cf.x, d11 = a1.y - cf.y;
            s0 = fmaf(d00, d00, s0); s0 = fmaf(d01, d01, s0);
            s1 = fmaf(d10, d10, s1); s1 = fmaf(d11, d11, s1);
        }
        #pragma unroll
        for (int off = 16; off; off >>= 1) {
            s0 += __shfl_xor_sync(0xffffffffu, s0, off);
            s1 += __shfl_xor_sync(0xffffffffu, s1, off);
        }
        if (lane == 0) { d2s[c][0] = s0; d2s[c][1] = s1; }
    }
    __syncthreads();

    if (tid < NS * KC) {
        int ns = tid >> 6, c = tid & 63;
        qv[ns][c] = 1.0f / (1.0f + d2s[c][ns]);
    }
    __syncthreads();

    if (tid < NS * 32) {
        int ns = tid >> 5, l = tid & 31;
        float s = qv[ns][l] + qv[ns][l + 32];
        #pragma unroll
        for (int off = 16; off; off >>= 1)
            s += __shfl_xor_sync(0xffffffffu, s, off);
        if (l == 0) ssum[ns] = s;
    }
    __syncthreads();

    if (tid < NS * KC) {
        int ns = tid >> 6, c = tid & 63;
        q[(size_t)(n0 + ns) * KC + c] = qv[ns][c] / ssum[ns];
    }
}

// ---------------------------------------------------------------------------
// Host side
// ---------------------------------------------------------------------------
template<int K>
static constexpr int conv_smem() { return (2 * 64 + K - 1) * 256 + 2 * 32768; }

extern "C" void kernel_launch(void* const* d_in, const int* in_sizes, int n_in,
                              void* d_out, int out_size)
{
    const float* x   = (const float*)d_in[0];
    const float* w1  = (const float*)d_in[1];
    const float* b1  = (const float*)d_in[2];
    const float* w2  = (const float*)d_in[3];
    const float* b2  = (const float*)d_in[4];
    const float* w3  = (const float*)d_in[5];
    const float* b3  = (const float*)d_in[6];
    const float* w4  = (const float*)d_in[7];
    const float* b4  = (const float*)d_in[8];
    const float* cen = (const float*)d_in[9];
    float* q = (float*)d_out;

    __half* xh;  cudaGetSymbolAddress((void**)&xh,  g_x);
    __half* h1;  cudaGetSymbolAddress((void**)&h1,  g_h1);
    __half* h2;  cudaGetSymbolAddress((void**)&h2,  g_h2);
    __half* h3;  cudaGetSymbolAddress((void**)&h3,  g_h3);
    __half* h4;  cudaGetSymbolAddress((void**)&h4,  g_h4);
    __half* wk;  cudaGetSymbolAddress((void**)&wk,  g_wk);
    __half* ch;  cudaGetSymbolAddress((void**)&ch,  g_cenh);

    cudaFuncSetAttribute(conv_mma<15, L1, LP0, LP1, true>,
        cudaFuncAttributeMaxDynamicSharedMemorySize, conv_smem<15>());
    cudaFuncSetAttribute(conv_mma<12, L2, LP1, LP2, true>,
        cudaFuncAttributeMaxDynamicSharedMemorySize, conv_smem<12>());
    cudaFuncSetAttribute(conv_mma<7,  L3, LP2, LP3, true>,
        cudaFuncAttributeMaxDynamicSharedMemorySize, conv_smem<7>());
    cudaFuncSetAttribute(conv_mma<4,  L4, LP3, LP4, false>,
        cudaFuncAttributeMaxDynamicSharedMemorySize, conv_smem<4>());
    cudaFuncSetAttribute(dist_kernel,
        cudaFuncAttributeMaxDynamicSharedMemorySize, NS * D * 2);

    // pre-passes
    transpose_x<<<dim3(L0 / 32, C / 32, N_BATCH), dim3(32, 8)>>>(x, xh);
    {
        int tot = W_ELEMS + KC * D;
        pack_all<<<(tot + 255) / 256, 256>>>(w1, w2, w3, w4, cen, wk, ch);
    }

    // conv stack (fp16 tensor-core mma, fp32 accumulate)
    conv_mma<15, L1, LP0, LP1, true><<<dim3(8, N_BATCH), 256, conv_smem<15>()>>>(
        xh, wk + (size_t)WKB1 * 16384, b1, h1);
    conv_mma<12, L2, LP1, LP2, true><<<dim3(4, N_BATCH), 256, conv_smem<12>()>>>(
        h1, wk + (size_t)WKB2 * 16384, b2, h2);
    conv_mma<7,  L3, LP2, LP3, true><<<dim3(2, N_BATCH), 256, conv_smem<7>()>>>(
        h2, wk + (size_t)WKB3 * 16384, b3, h3);
    conv_mma<4,  L4, LP3, LP4, false><<<dim3(1, N_BATCH), 256, conv_smem<4>()>>>(
        h3, wk + (size_t)WKB4 * 16384, b4, h4);

    dist_kernel<<<N_BATCH / NS, 256, NS * D * 2>>>(h4, ch, q);
}